// round 1
// baseline (speedup 1.0000x reference)
#include <cuda_runtime.h>

// Problem dims (fixed)
#define BB   4
#define NN   256
#define HH   4
#define CC   64
#define DIN  256
#define DFF  1024
#define PEH  128
#define BNTOK (BB*NN)          // 1024
#define PLANE (NN*NN)          // 65536
#define TOT   (BB*NN*DIN)      // 262144

// ---------------- scratch (static device globals; no allocation) ------------
__device__ float g_Q[TOT];
__device__ float g_K[TOT];
__device__ float g_V[TOT];
__device__ float g_psumT[BB*HH*PLANE];   // [B,H,N(j),N(k)]
__device__ float g_S[BB*HH*PLANE];       // scores / attn in place
__device__ float g_merged[TOT];
__device__ float g_res1[TOT];
__device__ float g_out1[TOT];
__device__ float g_res2[TOT];
__device__ float g_ffnh[BNTOK*DFF];
__device__ float g_pe2s[PEH*HH];         // folded pe2_w: [i][h]
__device__ float g_pe2bs[HH];            // folded pe2_b
__device__ float g_red[16];              // [ln_round(2)][b(4)][sum,sumsq]

// ---------------- fold pe2 over channel groups ------------------------------
__global__ void fold_k(const float* __restrict__ pe2w, const float* __restrict__ pe2b,
                       float* __restrict__ s2, float* __restrict__ sb2) {
    int i = threadIdx.x;  // 0..127
    #pragma unroll
    for (int h = 0; h < HH; h++) {
        float s = 0.f;
        #pragma unroll 8
        for (int c = 0; c < CC; c++) s += pe2w[i * (HH*CC) + h * CC + c];
        s2[i * HH + h] = s;
    }
    if (i < HH) {
        float s = 0.f;
        for (int c = 0; c < CC; c++) s += pe2b[i * CC + c];
        sb2[i] = s;
    }
}

// ---------------- PE MLP (folded): psumT[b,h,m,k] ---------------------------
__global__ void pe_k(const float* __restrict__ loc, const float* __restrict__ w1,
                     const float* __restrict__ b1, const float* __restrict__ s2,
                     const float* __restrict__ sb2, float* __restrict__ psumT) {
    __shared__ float4 sPack[PEH];  // (b1, w1_row0, w1_row1, w1_row2) per hidden unit
    __shared__ float4 sS4[PEH];    // folded pe2 per hidden unit (4 heads)
    __shared__ float  sSB[HH];
    int tid = threadIdx.x;
    if (tid < PEH) {
        sPack[tid] = make_float4(b1[tid], w1[tid], w1[PEH + tid], w1[2*PEH + tid]);
        sS4[tid]   = *(const float4*)(s2 + tid * 4);
    }
    if (tid < HH) sSB[tid] = sb2[tid];
    __syncthreads();

    int r = blockIdx.x * blockDim.x + tid;     // < 262144 rows (b,m,k)
    float c0 = loc[3*r], c1 = loc[3*r+1], c2 = loc[3*r+2];
    float a0 = sSB[0], a1 = sSB[1], a2 = sSB[2], a3 = sSB[3];
    #pragma unroll 8
    for (int i = 0; i < PEH; i++) {
        float4 wv = sPack[i];
        float hv = fmaf(c2, wv.w, fmaf(c1, wv.z, fmaf(c0, wv.y, wv.x)));
        hv = fmaxf(hv, 0.f);
        float4 sv = sS4[i];
        a0 = fmaf(hv, sv.x, a0);
        a1 = fmaf(hv, sv.y, a1);
        a2 = fmaf(hv, sv.z, a2);
        a3 = fmaf(hv, sv.w, a3);
    }
    int b = r >> 16, m = (r >> 8) & 255, k = r & 255;
    long base = (long)b * 4 * PLANE + (long)m * NN + k;
    psumT[base]            = a0;
    psumT[base + PLANE]    = a1;
    psumT[base + 2*PLANE]  = a2;
    psumT[base + 3*PLANE]  = a3;
}

// ---------------- generic NN GEMM: C = A[M,K] @ W[K,N] (+bias)(+resid)(relu) -
// BM=BN=64, BK=16, 256 threads, 4x4 register tile. M,N mult of 64, K mult of 16.
__global__ void gemm_nn_k(const float* __restrict__ A, const float* __restrict__ W,
                          const float* __restrict__ bias, const float* __restrict__ R,
                          float* __restrict__ Cout, int N, int K, int relu) {
    __shared__ float As[16][64];
    __shared__ float Bs[16][64];
    int tid = threadIdx.x;
    int tx = tid & 15, ty = tid >> 4;
    int bm = blockIdx.y * 64, bn = blockIdx.x * 64;
    int ar = tid >> 2, ac = (tid & 3) * 4;   // A tile: 64 rows x 16 cols via float4
    int br = tid >> 4, bc = (tid & 15) * 4;  // W tile: 16 rows x 64 cols via float4
    float acc[4][4] = {};
    for (int k0 = 0; k0 < K; k0 += 16) {
        float4 av = *(const float4*)(A + (long)(bm + ar) * K + k0 + ac);
        As[ac + 0][ar] = av.x; As[ac + 1][ar] = av.y;
        As[ac + 2][ar] = av.z; As[ac + 3][ar] = av.w;
        *(float4*)&Bs[br][bc] = *(const float4*)(W + (long)(k0 + br) * N + bn + bc);
        __syncthreads();
        #pragma unroll
        for (int k = 0; k < 16; k++) {
            float a0 = As[k][ty*4+0], a1 = As[k][ty*4+1], a2 = As[k][ty*4+2], a3 = As[k][ty*4+3];
            float b0 = Bs[k][tx*4+0], b1 = Bs[k][tx*4+1], b2 = Bs[k][tx*4+2], b3 = Bs[k][tx*4+3];
            acc[0][0]=fmaf(a0,b0,acc[0][0]); acc[0][1]=fmaf(a0,b1,acc[0][1]);
            acc[0][2]=fmaf(a0,b2,acc[0][2]); acc[0][3]=fmaf(a0,b3,acc[0][3]);
            acc[1][0]=fmaf(a1,b0,acc[1][0]); acc[1][1]=fmaf(a1,b1,acc[1][1]);
            acc[1][2]=fmaf(a1,b2,acc[1][2]); acc[1][3]=fmaf(a1,b3,acc[1][3]);
            acc[2][0]=fmaf(a2,b0,acc[2][0]); acc[2][1]=fmaf(a2,b1,acc[2][1]);
            acc[2][2]=fmaf(a2,b2,acc[2][2]); acc[2][3]=fmaf(a2,b3,acc[2][3]);
            acc[3][0]=fmaf(a3,b0,acc[3][0]); acc[3][1]=fmaf(a3,b1,acc[3][1]);
            acc[3][2]=fmaf(a3,b2,acc[3][2]); acc[3][3]=fmaf(a3,b3,acc[3][3]);
        }
        __syncthreads();
    }
    #pragma unroll
    for (int i = 0; i < 4; i++) {
        int row = bm + ty * 4 + i;
        #pragma unroll
        for (int j = 0; j < 4; j++) {
            int col = bn + tx * 4 + j;
            float v = acc[i][j];
            if (bias) v += bias[col];
            if (R)    v += R[(long)row * N + col];
            if (relu) v = fmaxf(v, 0.f);
            Cout[(long)row * N + col] = v;
        }
    }
}

// ---------------- scores: S[b,h,j,k] = (K_h[j]·Q_h[k] + psumT)*0.125 ---------
// NT gemm per (b,h): M=N=256, Kdim=64. grid (4,4,16)
__global__ void gemm_scores_k(const float* __restrict__ Km, const float* __restrict__ Qm,
                              const float* __restrict__ psumT, float* __restrict__ S) {
    int z = blockIdx.z, b = z >> 2, h = z & 3;
    const float* Ab = Km + (long)b * (NN*DIN) + h * CC;  // row stride DIN
    const float* Bb = Qm + (long)b * (NN*DIN) + h * CC;
    __shared__ float As[16][64];
    __shared__ float Bs[16][64];
    int tid = threadIdx.x;
    int tx = tid & 15, ty = tid >> 4;
    int bm = blockIdx.y * 64, bn = blockIdx.x * 64;
    int r = tid >> 2, c4 = (tid & 3) * 4;
    float acc[4][4] = {};
    for (int k0 = 0; k0 < CC; k0 += 16) {
        float4 av = *(const float4*)(Ab + (long)(bm + r) * DIN + k0 + c4);
        As[c4 + 0][r] = av.x; As[c4 + 1][r] = av.y; As[c4 + 2][r] = av.z; As[c4 + 3][r] = av.w;
        float4 bv = *(const float4*)(Bb + (long)(bn + r) * DIN + k0 + c4);
        Bs[c4 + 0][r] = bv.x; Bs[c4 + 1][r] = bv.y; Bs[c4 + 2][r] = bv.z; Bs[c4 + 3][r] = bv.w;
        __syncthreads();
        #pragma unroll
        for (int k = 0; k < 16; k++) {
            float a0 = As[k][ty*4+0], a1 = As[k][ty*4+1], a2 = As[k][ty*4+2], a3 = As[k][ty*4+3];
            float b0 = Bs[k][tx*4+0], b1 = Bs[k][tx*4+1], b2 = Bs[k][tx*4+2], b3 = Bs[k][tx*4+3];
            acc[0][0]=fmaf(a0,b0,acc[0][0]); acc[0][1]=fmaf(a0,b1,acc[0][1]);
            acc[0][2]=fmaf(a0,b2,acc[0][2]); acc[0][3]=fmaf(a0,b3,acc[0][3]);
            acc[1][0]=fmaf(a1,b0,acc[1][0]); acc[1][1]=fmaf(a1,b1,acc[1][1]);
            acc[1][2]=fmaf(a1,b2,acc[1][2]); acc[1][3]=fmaf(a1,b3,acc[1][3]);
            acc[2][0]=fmaf(a2,b0,acc[2][0]); acc[2][1]=fmaf(a2,b1,acc[2][1]);
            acc[2][2]=fmaf(a2,b2,acc[2][2]); acc[2][3]=fmaf(a2,b3,acc[2][3]);
            acc[3][0]=fmaf(a3,b0,acc[3][0]); acc[3][1]=fmaf(a3,b1,acc[3][1]);
            acc[3][2]=fmaf(a3,b2,acc[3][2]); acc[3][3]=fmaf(a3,b3,acc[3][3]);
        }
        __syncthreads();
    }
    long base = (long)z * PLANE;
    #pragma unroll
    for (int i = 0; i < 4; i++) {
        #pragma unroll
        for (int j = 0; j < 4; j++) {
            long idx = base + (long)(bm + ty*4 + i) * NN + bn + tx*4 + j;
            S[idx] = (acc[i][j] + psumT[idx]) * 0.125f;
        }
    }
}

// ---------------- softmax over last dim (256), one warp per row --------------
__global__ void softmax_k(float* __restrict__ S) {
    int t = threadIdx.x, warp = t >> 5, lane = t & 31;
    long row = (long)blockIdx.x * 8 + warp;   // < 4096
    float4* rp = (float4*)(S + row * NN);     // 64 float4
    float4 a = rp[lane];
    float4 b = rp[lane + 32];
    float mx = fmaxf(fmaxf(fmaxf(a.x, a.y), fmaxf(a.z, a.w)),
                     fmaxf(fmaxf(b.x, b.y), fmaxf(b.z, b.w)));
    #pragma unroll
    for (int o = 16; o > 0; o >>= 1) mx = fmaxf(mx, __shfl_xor_sync(0xffffffffu, mx, o));
    a.x = __expf(a.x - mx); a.y = __expf(a.y - mx); a.z = __expf(a.z - mx); a.w = __expf(a.w - mx);
    b.x = __expf(b.x - mx); b.y = __expf(b.y - mx); b.z = __expf(b.z - mx); b.w = __expf(b.w - mx);
    float sm = a.x + a.y + a.z + a.w + b.x + b.y + b.z + b.w;
    #pragma unroll
    for (int o = 16; o > 0; o >>= 1) sm += __shfl_xor_sync(0xffffffffu, sm, o);
    float inv = 1.f / sm;
    a.x *= inv; a.y *= inv; a.z *= inv; a.w *= inv;
    b.x *= inv; b.y *= inv; b.z *= inv; b.w *= inv;
    rp[lane] = a; rp[lane + 32] = b;
}

// ---------------- O = attn @ V_h, written to merged[b,j,h*64+c] --------------
// per (b,h): M=256, N=64, K=256. grid (1,4,16)
__global__ void gemm_av_k(const float* __restrict__ S, const float* __restrict__ Vm,
                          float* __restrict__ Mo) {
    int z = blockIdx.z, b = z >> 2, h = z & 3;
    const float* Ab = S + (long)z * PLANE;                // [256][256] contiguous
    const float* Wb = Vm + (long)b * (NN*DIN) + h * CC;   // W[k][c], row stride DIN
    __shared__ float As[16][64];
    __shared__ float Bs[16][64];
    int tid = threadIdx.x;
    int tx = tid & 15, ty = tid >> 4;
    int bm = blockIdx.y * 64;
    int ar = tid >> 2, ac = (tid & 3) * 4;
    int br = tid >> 4, bc = (tid & 15) * 4;
    float acc[4][4] = {};
    for (int k0 = 0; k0 < NN; k0 += 16) {
        float4 av = *(const float4*)(Ab + (long)(bm + ar) * NN + k0 + ac);
        As[ac + 0][ar] = av.x; As[ac + 1][ar] = av.y; As[ac + 2][ar] = av.z; As[ac + 3][ar] = av.w;
        *(float4*)&Bs[br][bc] = *(const float4*)(Wb + (long)(k0 + br) * DIN + bc);
        __syncthreads();
        #pragma unroll
        for (int k = 0; k < 16; k++) {
            float a0 = As[k][ty*4+0], a1 = As[k][ty*4+1], a2 = As[k][ty*4+2], a3 = As[k][ty*4+3];
            float b0 = Bs[k][tx*4+0], b1 = Bs[k][tx*4+1], b2 = Bs[k][tx*4+2], b3 = Bs[k][tx*4+3];
            acc[0][0]=fmaf(a0,b0,acc[0][0]); acc[0][1]=fmaf(a0,b1,acc[0][1]);
            acc[0][2]=fmaf(a0,b2,acc[0][2]); acc[0][3]=fmaf(a0,b3,acc[0][3]);
            acc[1][0]=fmaf(a1,b0,acc[1][0]); acc[1][1]=fmaf(a1,b1,acc[1][1]);
            acc[1][2]=fmaf(a1,b2,acc[1][2]); acc[1][3]=fmaf(a1,b3,acc[1][3]);
            acc[2][0]=fmaf(a2,b0,acc[2][0]); acc[2][1]=fmaf(a2,b1,acc[2][1]);
            acc[2][2]=fmaf(a2,b2,acc[2][2]); acc[2][3]=fmaf(a2,b3,acc[2][3]);
            acc[3][0]=fmaf(a3,b0,acc[3][0]); acc[3][1]=fmaf(a3,b1,acc[3][1]);
            acc[3][2]=fmaf(a3,b2,acc[3][2]); acc[3][3]=fmaf(a3,b3,acc[3][3]);
        }
        __syncthreads();
    }
    #pragma unroll
    for (int i = 0; i < 4; i++) {
        int j_out = bm + ty * 4 + i;
        #pragma unroll
        for (int j = 0; j < 4; j++) {
            int c = tx * 4 + j;
            Mo[((long)b * NN + j_out) * DIN + h * CC + c] = acc[i][j];
        }
    }
}

// ---------------- LayerNorm over [N,DIN] per batch ---------------------------
__global__ void zero_k(float* __restrict__ red) {
    if (threadIdx.x < 16) red[threadIdx.x] = 0.f;
}

__global__ void red_k(const float* __restrict__ X, float* __restrict__ red) {
    int b = blockIdx.y;
    const float* xb = X + (long)b * PLANE;
    float s = 0.f, q = 0.f;
    for (int i = blockIdx.x * blockDim.x + threadIdx.x; i < PLANE; i += gridDim.x * blockDim.x) {
        float v = xb[i];
        s += v;
        q = fmaf(v, v, q);
    }
    #pragma unroll
    for (int o = 16; o > 0; o >>= 1) {
        s += __shfl_xor_sync(0xffffffffu, s, o);
        q += __shfl_xor_sync(0xffffffffu, q, o);
    }
    __shared__ float sh[16];
    int lane = threadIdx.x & 31, warp = threadIdx.x >> 5;
    if (lane == 0) { sh[warp] = s; sh[8 + warp] = q; }
    __syncthreads();
    if (threadIdx.x == 0) {
        float ts = 0.f, tq = 0.f;
        #pragma unroll
        for (int i = 0; i < 8; i++) { ts += sh[i]; tq += sh[8 + i]; }
        atomicAdd(&red[b * 2], ts);
        atomicAdd(&red[b * 2 + 1], tq);
    }
}

__global__ void ln_k(const float* __restrict__ X, const float* __restrict__ w,
                     const float* __restrict__ bb, const float* __restrict__ red,
                     float* __restrict__ out) {
    int idx = blockIdx.x * blockDim.x + threadIdx.x;  // < 262144
    int b = idx >> 16;
    float m   = red[b * 2] * (1.f / 65536.f);
    float var = red[b * 2 + 1] * (1.f / 65536.f) - m * m;
    float ri  = rsqrtf(var + 1e-5f);
    int p = idx & 65535;
    out[idx] = (X[idx] - m) * ri * w[p] + bb[p];
}

// ---------------- launch ------------------------------------------------------
extern "C" void kernel_launch(void* const* d_in, const int* in_sizes, int n_in,
                              void* d_out, int out_size) {
    const float* feat   = (const float*)d_in[0];
    const float* loc    = (const float*)d_in[1];
    const float* Kw     = (const float*)d_in[2];
    const float* Kb     = (const float*)d_in[3];
    const float* Qw     = (const float*)d_in[4];
    const float* Qb     = (const float*)d_in[5];
    const float* Vw     = (const float*)d_in[6];
    const float* Vb     = (const float*)d_in[7];
    const float* Fw     = (const float*)d_in[8];
    const float* Fb     = (const float*)d_in[9];
    const float* pe1w   = (const float*)d_in[10];
    const float* pe1b   = (const float*)d_in[11];
    const float* pe2w   = (const float*)d_in[12];
    const float* pe2b   = (const float*)d_in[13];
    const float* f1w    = (const float*)d_in[14];
    const float* f1b    = (const float*)d_in[15];
    const float* f2w    = (const float*)d_in[16];
    const float* f2b    = (const float*)d_in[17];
    const float* ln1w   = (const float*)d_in[18];
    const float* ln1b   = (const float*)d_in[19];
    const float* ln2w   = (const float*)d_in[20];
    const float* ln2b   = (const float*)d_in[21];
    float* out = (float*)d_out;

    float *pQ, *pK, *pV, *pPsum, *pS, *pMerged, *pRes1, *pOut1, *pRes2, *pFfnh;
    float *pPe2s, *pPe2bs, *pRed;
    cudaGetSymbolAddress((void**)&pQ, g_Q);
    cudaGetSymbolAddress((void**)&pK, g_K);
    cudaGetSymbolAddress((void**)&pV, g_V);
    cudaGetSymbolAddress((void**)&pPsum, g_psumT);
    cudaGetSymbolAddress((void**)&pS, g_S);
    cudaGetSymbolAddress((void**)&pMerged, g_merged);
    cudaGetSymbolAddress((void**)&pRes1, g_res1);
    cudaGetSymbolAddress((void**)&pOut1, g_out1);
    cudaGetSymbolAddress((void**)&pRes2, g_res2);
    cudaGetSymbolAddress((void**)&pFfnh, g_ffnh);
    cudaGetSymbolAddress((void**)&pPe2s, g_pe2s);
    cudaGetSymbolAddress((void**)&pPe2bs, g_pe2bs);
    cudaGetSymbolAddress((void**)&pRed, g_red);

    // fold pe2 (tiny) + zero LN accumulators
    fold_k<<<1, 128>>>(pe2w, pe2b, pPe2s, pPe2bs);
    zero_k<<<1, 32>>>(pRed);

    // QKV projections: [1024,256] @ [256,256]
    dim3 gQKV(DIN / 64, BNTOK / 64);
    gemm_nn_k<<<gQKV, 256>>>(feat, Qw, Qb, nullptr, pQ, DIN, DIN, 0);
    gemm_nn_k<<<gQKV, 256>>>(feat, Kw, Kb, nullptr, pK, DIN, DIN, 0);
    gemm_nn_k<<<gQKV, 256>>>(feat, Vw, Vb, nullptr, pV, DIN, DIN, 0);

    // PE (folded) -> psumT[B,H,N,N]
    pe_k<<<BB * NN * NN / 256, 256>>>(loc, pe1w, pe1b, pPe2s, pPe2bs, pPsum);

    // scores + bias + scale, softmax, attn @ V
    gemm_scores_k<<<dim3(4, 4, BB * HH), 256>>>(pK, pQ, pPsum, pS);
    softmax_k<<<BB * HH * NN / 8, 256>>>(pS);
    gemm_av_k<<<dim3(1, 4, BB * HH), 256>>>(pS, pV, pMerged);

    // output projection + residual
    gemm_nn_k<<<gQKV, 256>>>(pMerged, Fw, Fb, feat, pRes1, DIN, DIN, 0);

    // LN1
    red_k<<<dim3(32, BB), 256>>>(pRes1, pRed);
    ln_k<<<TOT / 256, 256>>>(pRes1, ln1w, ln1b, pRed, pOut1);

    // FFN
    gemm_nn_k<<<dim3(DFF / 64, BNTOK / 64), 256>>>(pOut1, f1w, f1b, nullptr, pFfnh, DFF, DIN, 1);
    gemm_nn_k<<<gQKV, 256>>>(pFfnh, f2w, f2b, pOut1, pRes2, DIN, DFF, 0);

    // LN2 -> output
    red_k<<<dim3(32, BB), 256>>>(pRes2, pRed + 8);
    ln_k<<<TOT / 256, 256>>>(pRes2, ln2w, ln2b, pRed + 8, out);
}

// round 2
// speedup vs baseline: 1.1363x; 1.1363x over previous
#include <cuda_runtime.h>

#define BBATCH 4
#define NSEQ   256
#define HHEADS 4
#define CDIM   64
#define DIN    256
#define DFF    1024
#define PEH    128
#define BNTOK  1024
#define PLANE  65536
#define TOT    262144
#define QKVW   768

typedef unsigned long long ull;

__device__ __forceinline__ ull pk2(float x, float y) {
    ull r; asm("mov.b64 %0, {%1,%2};" : "=l"(r) : "f"(x), "f"(y)); return r;
}
__device__ __forceinline__ void upk2(ull v, float& x, float& y) {
    asm("mov.b64 {%0,%1}, %2;" : "=f"(x), "=f"(y) : "l"(v));
}
__device__ __forceinline__ ull ffma2(ull a, ull b, ull c) {
    ull d; asm("fma.rn.f32x2 %0, %1, %2, %3;" : "=l"(d) : "l"(a), "l"(b), "l"(c)); return d;
}

// ---------------- scratch ----------------------------------------------------
__device__ float g_QKV[BNTOK * QKVW];
__device__ float g_Wqkv[DIN * QKVW];
__device__ float g_Bqkv[QKVW];
__device__ float g_psum[BBATCH * HHEADS * PLANE];
__device__ float g_S[BBATCH * HHEADS * PLANE];
__device__ float g_merged[TOT];
__device__ float g_res1[TOT];
__device__ float g_out1[TOT];
__device__ float g_res2[TOT];
__device__ float g_ffnh[BNTOK * DFF];
__device__ float g_pe2s[PEH * HHEADS];
__device__ float g_pe2bs[HHEADS];
__device__ float g_red[16];

// ---------------- prep: pack QKV weights, fold pe2, zero LN accumulators -----
__global__ void prep_k(const float* __restrict__ Qw, const float* __restrict__ Kw,
                       const float* __restrict__ Vw, const float* __restrict__ Qb,
                       const float* __restrict__ Kb, const float* __restrict__ Vb,
                       const float* __restrict__ pe2w, const float* __restrict__ pe2b) {
    int blk = blockIdx.x, tid = threadIdx.x;
    if (blk < 192) {
        int o = blk * 256 + tid;           // float4 index < 49152
        int k = o / 192;
        int jc = (o % 192) * 4;
        const float* src = (jc < 256) ? Qw : (jc < 512 ? Kw : Vw);
        int col = jc & 255;
        float4 v = *(const float4*)(src + k * 256 + col);
        *(float4*)(g_Wqkv + k * 768 + jc) = v;
    } else {
        for (int j = tid; j < 768; j += 256) {
            const float* sb = (j < 256) ? Qb : (j < 512 ? Kb : Vb);
            g_Bqkv[j] = sb[j & 255];
        }
        if (tid < 128) {
            int i = tid;
            #pragma unroll
            for (int h = 0; h < 4; h++) {
                float s = 0.f;
                #pragma unroll 8
                for (int c = 0; c < 64; c++) s += pe2w[i * 256 + h * 64 + c];
                g_pe2s[i * 4 + h] = s;
            }
        }
        if (tid < 4) {
            float s = 0.f;
            for (int c = 0; c < 64; c++) s += pe2b[tid * 64 + c];
            g_pe2bs[tid] = s;
        }
        if (tid < 16) g_red[tid] = 0.f;
    }
}

// ---------------- PE MLP, folded, 2 rows/thread with f32x2 -------------------
__global__ void pe_k(const float* __restrict__ loc, const float* __restrict__ w1,
                     const float* __restrict__ b1) {
    __shared__ float4 sW[PEH];
    __shared__ ull    sS[PEH][4];
    __shared__ float  sB[4];
    int tid = threadIdx.x;
    if (tid < PEH) {
        sW[tid] = make_float4(b1[tid], w1[tid], w1[PEH + tid], w1[2 * PEH + tid]);
        float4 sv = *(const float4*)(g_pe2s + tid * 4);
        sS[tid][0] = pk2(sv.x, sv.x);
        sS[tid][1] = pk2(sv.y, sv.y);
        sS[tid][2] = pk2(sv.z, sv.z);
        sS[tid][3] = pk2(sv.w, sv.w);
    }
    if (tid < 4) sB[tid] = g_pe2bs[tid];
    __syncthreads();

    int gid = blockIdx.x * 256 + tid;      // < 131072, two rows each
    const float2* L = (const float2*)loc;
    float2 l0 = L[3 * gid], l1 = L[3 * gid + 1], l2 = L[3 * gid + 2];
    // row0 coords (l0.x, l0.y, l1.x); row1 coords (l1.y, l2.x, l2.y)
    ull A0 = pk2(sB[0], sB[0]), A1 = pk2(sB[1], sB[1]);
    ull A2 = pk2(sB[2], sB[2]), A3 = pk2(sB[3], sB[3]);
    #pragma unroll 4
    for (int i = 0; i < PEH; i++) {
        float4 w = sW[i];
        float h0 = fmaf(l1.x, w.w, fmaf(l0.y, w.z, fmaf(l0.x, w.y, w.x)));
        float h1 = fmaf(l2.y, w.w, fmaf(l2.x, w.z, fmaf(l1.y, w.y, w.x)));
        h0 = fmaxf(h0, 0.f); h1 = fmaxf(h1, 0.f);
        ull hd = pk2(h0, h1);
        A0 = ffma2(hd, sS[i][0], A0);
        A1 = ffma2(hd, sS[i][1], A1);
        A2 = ffma2(hd, sS[i][2], A2);
        A3 = ffma2(hd, sS[i][3], A3);
    }
    int r0 = 2 * gid;
    int b = r0 >> 16, m = (r0 >> 8) & 255, k2 = (r0 & 255) >> 1;
    float2* P = (float2*)g_psum;
    long base = ((long)b * 4) * 32768 + (long)m * 128 + k2;  // float2 units
    float x, y;
    upk2(A0, x, y); P[base]              = make_float2(x, y);
    upk2(A1, x, y); P[base + 32768]      = make_float2(x, y);
    upk2(A2, x, y); P[base + 2 * 32768]  = make_float2(x, y);
    upk2(A3, x, y); P[base + 3 * 32768]  = make_float2(x, y);
}

// ---------------- templated f32x2 GEMM ---------------------------------------
// C[M,N] = A[M,K] @ B  (B row-major [K,N], or TRB: B rows [N,K] dotted along K)
// TM=TN=4 per thread, BK=16, double-buffered smem, A pre-duplicated for f32x2.
#define EPI_BIAS  0
#define EPI_BRELU 1
#define EPI_BRR   2   /* bias + residual + LN sum/sumsq atomics */
#define EPI_SC    3   /* (acc + psum)*0.125 */
#define EPI_NONE  4

template<int BM, int BN, int NTHR, int TRB, int EPI>
__global__ void gemm2(const float* __restrict__ A, const float* __restrict__ B,
                      const float* __restrict__ bias, const float* __restrict__ R,
                      float* __restrict__ C, const float* __restrict__ psum,
                      float* __restrict__ red,
                      int K, int lda, int ldb, int ldc,
                      long sAb, long sAh, long sBb, long sBh, long sCb, long sCh) {
    constexpr int TM = 4, TN = 4;
    constexpr int TCOLS = BN / TN;
    constexpr int ASLOT = BM * 16 / 4;
    constexpr int BSLOT = BN * 16 / 4;
    constexpr int APT = ASLOT / NTHR;
    constexpr int BPT = BSLOT / NTHR;
    __shared__ float As[2][16][2 * BM];
    __shared__ float Bs[2][16][BN];
    __shared__ float shr[2][NTHR / 32];

    int tid = threadIdx.x;
    int z = blockIdx.z, zb = z >> 2, zh = z & 3;
    const float* Ab = A + (long)zb * sAb + (long)zh * sAh + (long)(blockIdx.y * BM) * lda;
    const float* Bb;
    if (TRB) Bb = B + (long)zb * sBb + (long)zh * sBh + (long)(blockIdx.x * BN) * ldb;
    else     Bb = B + (long)zb * sBb + (long)zh * sBh + blockIdx.x * BN;

    int aR[APT], aC[APT], bR[BPT], bC[BPT];
    #pragma unroll
    for (int t = 0; t < APT; t++) { int s = tid + t * NTHR; aR[t] = s >> 2; aC[t] = (s & 3) * 4; }
    #pragma unroll
    for (int t = 0; t < BPT; t++) {
        int s = tid + t * NTHR;
        if (TRB) { bR[t] = s >> 2; bC[t] = (s & 3) * 4; }
        else     { bR[t] = s / (BN / 4); bC[t] = (s % (BN / 4)) * 4; }
    }
    float4 rA[APT], rB[BPT];

    auto ldg = [&](int kt) {
        #pragma unroll
        for (int t = 0; t < APT; t++)
            rA[t] = *(const float4*)(Ab + (long)aR[t] * lda + kt * 16 + aC[t]);
        #pragma unroll
        for (int t = 0; t < BPT; t++) {
            if (TRB) rB[t] = *(const float4*)(Bb + (long)bR[t] * ldb + kt * 16 + bC[t]);
            else     rB[t] = *(const float4*)(Bb + (long)(kt * 16 + bR[t]) * ldb + bC[t]);
        }
    };
    auto sts = [&](int bf) {
        #pragma unroll
        for (int t = 0; t < APT; t++) {
            float4 v = rA[t]; int r2 = 2 * aR[t];
            *(float2*)&As[bf][aC[t] + 0][r2] = make_float2(v.x, v.x);
            *(float2*)&As[bf][aC[t] + 1][r2] = make_float2(v.y, v.y);
            *(float2*)&As[bf][aC[t] + 2][r2] = make_float2(v.z, v.z);
            *(float2*)&As[bf][aC[t] + 3][r2] = make_float2(v.w, v.w);
        }
        #pragma unroll
        for (int t = 0; t < BPT; t++) {
            float4 v = rB[t];
            if (TRB) {
                int r = bR[t];
                Bs[bf][bC[t] + 0][r] = v.x; Bs[bf][bC[t] + 1][r] = v.y;
                Bs[bf][bC[t] + 2][r] = v.z; Bs[bf][bC[t] + 3][r] = v.w;
            } else {
                *(float4*)&Bs[bf][bR[t]][bC[t]] = v;
            }
        }
    };

    int tx = tid % TCOLS, ty = tid / TCOLS;
    ull acc[TM][TN / 2] = {};
    int KT = K / 16, buf = 0;

    ldg(0); sts(0); __syncthreads();
    for (int kt = 0; kt < KT; kt++) {
        if (kt + 1 < KT) ldg(kt + 1);
        #pragma unroll
        for (int k = 0; k < 16; k++) {
            ull a0 = *(ull*)&As[buf][k][2 * (ty * TM) + 0];
            ull a1 = *(ull*)&As[buf][k][2 * (ty * TM) + 2];
            ull a2 = *(ull*)&As[buf][k][2 * (ty * TM) + 4];
            ull a3 = *(ull*)&As[buf][k][2 * (ty * TM) + 6];
            ull b0 = *(ull*)&Bs[buf][k][tx * TN + 0];
            ull b1 = *(ull*)&Bs[buf][k][tx * TN + 2];
            acc[0][0] = ffma2(a0, b0, acc[0][0]); acc[0][1] = ffma2(a0, b1, acc[0][1]);
            acc[1][0] = ffma2(a1, b0, acc[1][0]); acc[1][1] = ffma2(a1, b1, acc[1][1]);
            acc[2][0] = ffma2(a2, b0, acc[2][0]); acc[2][1] = ffma2(a2, b1, acc[2][1]);
            acc[3][0] = ffma2(a3, b0, acc[3][0]); acc[3][1] = ffma2(a3, b1, acc[3][1]);
        }
        if (kt + 1 < KT) { sts(buf ^ 1); __syncthreads(); buf ^= 1; }
    }

    long Coff = (long)zb * sCb + (long)zh * sCh;
    int row0 = blockIdx.y * BM + ty * TM;
    int col0 = blockIdx.x * BN + tx * TN;
    float sum = 0.f, sq = 0.f;
    #pragma unroll
    for (int i = 0; i < TM; i++) {
        #pragma unroll
        for (int j = 0; j < TN / 2; j++) {
            float x, y; upk2(acc[i][j], x, y);
            int c = col0 + 2 * j;
            long idx = Coff + (long)(row0 + i) * ldc + c;
            if (EPI == EPI_BIAS)  { x += bias[c]; y += bias[c + 1]; }
            if (EPI == EPI_BRELU) { x = fmaxf(x + bias[c], 0.f); y = fmaxf(y + bias[c + 1], 0.f); }
            if (EPI == EPI_BRR) {
                float2 rv = *(const float2*)(R + idx);
                x += bias[c] + rv.x; y += bias[c + 1] + rv.y;
                sum += x + y; sq += x * x + y * y;
            }
            if (EPI == EPI_SC) {
                float2 pv = *(const float2*)(psum + idx);
                x = (x + pv.x) * 0.125f; y = (y + pv.y) * 0.125f;
            }
            *(float2*)(C + idx) = make_float2(x, y);
        }
    }
    if (EPI == EPI_BRR) {
        #pragma unroll
        for (int o = 16; o > 0; o >>= 1) {
            sum += __shfl_xor_sync(0xffffffffu, sum, o);
            sq  += __shfl_xor_sync(0xffffffffu, sq, o);
        }
        int ln = tid & 31, wp = tid >> 5;
        if (ln == 0) { shr[0][wp] = sum; shr[1][wp] = sq; }
        __syncthreads();
        if (tid == 0) {
            float ts = 0.f, tq = 0.f;
            #pragma unroll
            for (int w = 0; w < NTHR / 32; w++) { ts += shr[0][w]; tq += shr[1][w]; }
            int bat = (blockIdx.y * BM) >> 8;
            atomicAdd(&red[bat * 2], ts);
            atomicAdd(&red[bat * 2 + 1], tq);
        }
    }
}

// ---------------- softmax over last dim (256), one warp per row --------------
__global__ void softmax_k(float* __restrict__ S) {
    int t = threadIdx.x, warp = t >> 5, lane = t & 31;
    long row = (long)blockIdx.x * 8 + warp;
    float4* rp = (float4*)(S + row * NSEQ);
    float4 a = rp[lane];
    float4 b = rp[lane + 32];
    float mx = fmaxf(fmaxf(fmaxf(a.x, a.y), fmaxf(a.z, a.w)),
                     fmaxf(fmaxf(b.x, b.y), fmaxf(b.z, b.w)));
    #pragma unroll
    for (int o = 16; o > 0; o >>= 1) mx = fmaxf(mx, __shfl_xor_sync(0xffffffffu, mx, o));
    a.x = __expf(a.x - mx); a.y = __expf(a.y - mx); a.z = __expf(a.z - mx); a.w = __expf(a.w - mx);
    b.x = __expf(b.x - mx); b.y = __expf(b.y - mx); b.z = __expf(b.z - mx); b.w = __expf(b.w - mx);
    float sm = a.x + a.y + a.z + a.w + b.x + b.y + b.z + b.w;
    #pragma unroll
    for (int o = 16; o > 0; o >>= 1) sm += __shfl_xor_sync(0xffffffffu, sm, o);
    float inv = 1.f / sm;
    a.x *= inv; a.y *= inv; a.z *= inv; a.w *= inv;
    b.x *= inv; b.y *= inv; b.z *= inv; b.w *= inv;
    rp[lane] = a; rp[lane + 32] = b;
}

// ---------------- LayerNorm apply (stats from red) ---------------------------
__global__ void ln_k(const float* __restrict__ X, const float* __restrict__ w,
                     const float* __restrict__ b, const float* __restrict__ red,
                     float* __restrict__ out) {
    int g = blockIdx.x * blockDim.x + threadIdx.x;   // < 65536 float4s
    int bt = g >> 14;
    float m   = red[bt * 2] * (1.f / 65536.f);
    float var = red[bt * 2 + 1] * (1.f / 65536.f) - m * m;
    float ri  = rsqrtf(var + 1e-5f);
    int p = g & 16383;
    float4 x  = ((const float4*)X)[g];
    float4 wv = ((const float4*)w)[p];
    float4 bv = ((const float4*)b)[p];
    float4 o;
    o.x = (x.x - m) * ri * wv.x + bv.x;
    o.y = (x.y - m) * ri * wv.y + bv.y;
    o.z = (x.z - m) * ri * wv.z + bv.z;
    o.w = (x.w - m) * ri * wv.w + bv.w;
    ((float4*)out)[g] = o;
}

// ---------------- launch ------------------------------------------------------
extern "C" void kernel_launch(void* const* d_in, const int* in_sizes, int n_in,
                              void* d_out, int out_size) {
    const float* feat = (const float*)d_in[0];
    const float* loc  = (const float*)d_in[1];
    const float* Kw   = (const float*)d_in[2];
    const float* Kb   = (const float*)d_in[3];
    const float* Qw   = (const float*)d_in[4];
    const float* Qb   = (const float*)d_in[5];
    const float* Vw   = (const float*)d_in[6];
    const float* Vb   = (const float*)d_in[7];
    const float* Fw   = (const float*)d_in[8];
    const float* Fb   = (const float*)d_in[9];
    const float* pe1w = (const float*)d_in[10];
    const float* pe1b = (const float*)d_in[11];
    const float* pe2w = (const float*)d_in[12];
    const float* pe2b = (const float*)d_in[13];
    const float* f1w  = (const float*)d_in[14];
    const float* f1b  = (const float*)d_in[15];
    const float* f2w  = (const float*)d_in[16];
    const float* f2b  = (const float*)d_in[17];
    const float* ln1w = (const float*)d_in[18];
    const float* ln1b = (const float*)d_in[19];
    const float* ln2w = (const float*)d_in[20];
    const float* ln2b = (const float*)d_in[21];
    float* out = (float*)d_out;

    float *pQKV, *pW, *pBq, *pPsum, *pS, *pMerged, *pRes1, *pOut1, *pRes2, *pFfnh, *pRed;
    cudaGetSymbolAddress((void**)&pQKV, g_QKV);
    cudaGetSymbolAddress((void**)&pW, g_Wqkv);
    cudaGetSymbolAddress((void**)&pBq, g_Bqkv);
    cudaGetSymbolAddress((void**)&pPsum, g_psum);
    cudaGetSymbolAddress((void**)&pS, g_S);
    cudaGetSymbolAddress((void**)&pMerged, g_merged);
    cudaGetSymbolAddress((void**)&pRes1, g_res1);
    cudaGetSymbolAddress((void**)&pOut1, g_out1);
    cudaGetSymbolAddress((void**)&pRes2, g_res2);
    cudaGetSymbolAddress((void**)&pFfnh, g_ffnh);
    cudaGetSymbolAddress((void**)&pRed, g_red);

    prep_k<<<193, 256>>>(Qw, Kw, Vw, Qb, Kb, Vb, pe2w, pe2b);

    // PE MLP (folded) -> psum[B,H,N,N]
    pe_k<<<512, 256>>>(loc, pe1w, pe1b);

    // fused QKV projection: [1024,256] @ [256,768]
    gemm2<64, 64, 256, 0, EPI_BIAS><<<dim3(12, 16, 1), 256>>>(
        feat, pW, pBq, nullptr, pQKV, nullptr, nullptr,
        256, 256, 768, 768, 0, 0, 0, 0, 0, 0);

    // scores: per (b,h) K-rows · Q-rows^T + psum, scaled
    gemm2<64, 64, 256, 1, EPI_SC><<<dim3(4, 4, 16), 256>>>(
        pQKV + 256, pQKV, nullptr, nullptr, pS, pPsum, nullptr,
        64, 768, 768, 256, 196608, 64, 196608, 64, 262144, 65536);

    softmax_k<<<512, 256>>>(pS);

    // merged = attn @ V
    gemm2<32, 64, 128, 0, EPI_NONE><<<dim3(1, 8, 16), 128>>>(
        pS, pQKV + 512, nullptr, nullptr, pMerged, nullptr, nullptr,
        256, 256, 768, 256, 262144, 65536, 196608, 64, 65536, 64);

    // output projection + residual + LN1 reduce
    gemm2<64, 32, 128, 0, EPI_BRR><<<dim3(8, 16, 1), 128>>>(
        pMerged, Fw, Fb, feat, pRes1, nullptr, pRed,
        256, 256, 256, 256, 0, 0, 0, 0, 0, 0);
    ln_k<<<256, 256>>>(pRes1, ln1w, ln1b, pRed, pOut1);

    // FFN
    gemm2<64, 64, 256, 0, EPI_BRELU><<<dim3(16, 16, 1), 256>>>(
        pOut1, f1w, f1b, nullptr, pFfnh, nullptr, nullptr,
        256, 256, 1024, 1024, 0, 0, 0, 0, 0, 0);
    gemm2<64, 32, 128, 0, EPI_BRR><<<dim3(8, 16, 1), 128>>>(
        pFfnh, f2w, f2b, pOut1, pRes2, nullptr, pRed + 8,
        1024, 1024, 256, 256, 0, 0, 0, 0, 0, 0);
    ln_k<<<256, 256>>>(pRes2, ln2w, ln2b, pRed + 8, out);
}

// round 3
// speedup vs baseline: 2.1612x; 1.9020x over previous
#include <cuda_runtime.h>

#define BBATCH 4
#define NSEQ   256
#define HHEADS 4
#define CDIM   64
#define DIN    256
#define DFF    1024
#define PEH    128
#define BNTOK  1024
#define PLANE  65536
#define TOT    262144
#define QKVW   768

typedef unsigned long long ull;

__device__ __forceinline__ ull pk2(float x, float y) {
    ull r; asm("mov.b64 %0, {%1,%2};" : "=l"(r) : "f"(x), "f"(y)); return r;
}
__device__ __forceinline__ void upk2(ull v, float& x, float& y) {
    asm("mov.b64 {%0,%1}, %2;" : "=f"(x), "=f"(y) : "l"(v));
}
__device__ __forceinline__ ull ffma2(ull a, ull b, ull c) {
    ull d; asm("fma.rn.f32x2 %0, %1, %2, %3;" : "=l"(d) : "l"(a), "l"(b), "l"(c)); return d;
}
__device__ __forceinline__ unsigned f2t(float x) {
    unsigned u; asm("cvt.rna.tf32.f32 %0, %1;" : "=r"(u) : "f"(x)); return u;
}
__device__ __forceinline__ void mma8(float& d0, float& d1, float& d2, float& d3,
                                     unsigned a0, unsigned a1, unsigned a2, unsigned a3,
                                     unsigned b0, unsigned b1) {
    asm volatile("mma.sync.aligned.m16n8k8.row.col.f32.tf32.tf32.f32 "
                 "{%0,%1,%2,%3}, {%4,%5,%6,%7}, {%8,%9}, {%0,%1,%2,%3};"
                 : "+f"(d0), "+f"(d1), "+f"(d2), "+f"(d3)
                 : "r"(a0), "r"(a1), "r"(a2), "r"(a3), "r"(b0), "r"(b1));
}

// ---------------- scratch ----------------------------------------------------
__device__ float g_QKV[BNTOK * QKVW];
__device__ float g_Wqkv[DIN * QKVW];
__device__ float g_Bqkv[QKVW];
__device__ float g_psum[BBATCH * HHEADS * PLANE];
__device__ float g_S[BBATCH * HHEADS * PLANE];
__device__ float g_avp[2 * TOT];
__device__ float g_part[4 * TOT];
__device__ float g_res1[TOT];
__device__ float g_out1[TOT];
__device__ float g_res2[TOT];
__device__ float g_ffnh[BNTOK * DFF];
__device__ float g_pe2s[PEH * HHEADS];
__device__ float g_pe2bs[HHEADS];
__device__ float g_red[16];

// ---------------- prep: pack QKV weights, fold pe2, zero LN accumulators -----
__global__ void prep_k(const float* __restrict__ Qw, const float* __restrict__ Kw,
                       const float* __restrict__ Vw, const float* __restrict__ Qb,
                       const float* __restrict__ Kb, const float* __restrict__ Vb,
                       const float* __restrict__ pe2w, const float* __restrict__ pe2b) {
    int blk = blockIdx.x, tid = threadIdx.x;
    if (blk < 192) {
        int o = blk * 256 + tid;
        int k = o / 192;
        int jc = (o % 192) * 4;
        const float* src = (jc < 256) ? Qw : (jc < 512 ? Kw : Vw);
        int col = jc & 255;
        float4 v = *(const float4*)(src + k * 256 + col);
        *(float4*)(g_Wqkv + k * 768 + jc) = v;
    } else {
        for (int j = tid; j < 768; j += 256) {
            const float* sb = (j < 256) ? Qb : (j < 512 ? Kb : Vb);
            g_Bqkv[j] = sb[j & 255];
        }
        if (tid < 128) {
            int i = tid;
            #pragma unroll
            for (int h = 0; h < 4; h++) {
                float s = 0.f;
                #pragma unroll 8
                for (int c = 0; c < 64; c++) s += pe2w[i * 256 + h * 64 + c];
                g_pe2s[i * 4 + h] = s;
            }
        }
        if (tid < 4) {
            float s = 0.f;
            for (int c = 0; c < 64; c++) s += pe2b[tid * 64 + c];
            g_pe2bs[tid] = s;
        }
        if (tid < 16) g_red[tid] = 0.f;
    }
}

// ---------------- PE MLP, folded, 2 rows/thread with f32x2 -------------------
__global__ void pe_k(const float* __restrict__ loc, const float* __restrict__ w1,
                     const float* __restrict__ b1) {
    __shared__ float4 sW[PEH];
    __shared__ ull    sS[PEH][4];
    __shared__ float  sB[4];
    int tid = threadIdx.x;
    if (tid < PEH) {
        sW[tid] = make_float4(b1[tid], w1[tid], w1[PEH + tid], w1[2 * PEH + tid]);
        float4 sv = *(const float4*)(g_pe2s + tid * 4);
        sS[tid][0] = pk2(sv.x, sv.x);
        sS[tid][1] = pk2(sv.y, sv.y);
        sS[tid][2] = pk2(sv.z, sv.z);
        sS[tid][3] = pk2(sv.w, sv.w);
    }
    if (tid < 4) sB[tid] = g_pe2bs[tid];
    __syncthreads();

    int gid = blockIdx.x * 256 + tid;
    const float2* L = (const float2*)loc;
    float2 l0 = L[3 * gid], l1 = L[3 * gid + 1], l2 = L[3 * gid + 2];
    ull A0 = pk2(sB[0], sB[0]), A1 = pk2(sB[1], sB[1]);
    ull A2 = pk2(sB[2], sB[2]), A3 = pk2(sB[3], sB[3]);
    #pragma unroll 4
    for (int i = 0; i < PEH; i++) {
        float4 w = sW[i];
        float h0 = fmaf(l1.x, w.w, fmaf(l0.y, w.z, fmaf(l0.x, w.y, w.x)));
        float h1 = fmaf(l2.y, w.w, fmaf(l2.x, w.z, fmaf(l1.y, w.y, w.x)));
        h0 = fmaxf(h0, 0.f); h1 = fmaxf(h1, 0.f);
        ull hd = pk2(h0, h1);
        A0 = ffma2(hd, sS[i][0], A0);
        A1 = ffma2(hd, sS[i][1], A1);
        A2 = ffma2(hd, sS[i][2], A2);
        A3 = ffma2(hd, sS[i][3], A3);
    }
    int r0 = 2 * gid;
    int b = r0 >> 16, m = (r0 >> 8) & 255, k2 = (r0 & 255) >> 1;
    float2* P = (float2*)g_psum;
    long base = ((long)b * 4) * 32768 + (long)m * 128 + k2;
    float x, y;
    upk2(A0, x, y); P[base]             = make_float2(x, y);
    upk2(A1, x, y); P[base + 32768]     = make_float2(x, y);
    upk2(A2, x, y); P[base + 2 * 32768] = make_float2(x, y);
    upk2(A3, x, y); P[base + 3 * 32768] = make_float2(x, y);
}

// ---------------- TF32 tensor-core GEMM --------------------------------------
// Warp tile 32x32 = 2 x 4 of m16n8k8. Block BM=WR*32, BN=WC*32. BK-step smem
// double buffered, TF32 conversion at STS. TRB: B stored [N,K] (NT gemm).
// Split-K via blockIdx.x / NBL, each split writes C + sp*spC.
#define EPI_NONE  0
#define EPI_BIAS  1
#define EPI_BRELU 2
#define EPI_SC    3

template<int WR, int WC, int BK, int TRB, int EPI, int ASUM, int NBL>
__global__ void gtc(const float* __restrict__ A, const float* __restrict__ A2,
                    const float* __restrict__ B, const float* __restrict__ bias,
                    float* __restrict__ C, const float* __restrict__ psum,
                    int KSPL, int lda, int ldb, int ldc,
                    long sAb, long sAh, long sBb, long sBh, long sCb, long sCh,
                    long spC) {
    constexpr int BM = WR * 32, BN = WC * 32, NTHR = WR * WC * 32;
    constexpr int APT = BM * BK / 4 / NTHR;
    constexpr int BPT = BN * BK / 4 / NTHR;
    __shared__ unsigned As[2][BK][BM + 8];
    __shared__ unsigned Bs[2][BK][BN + 8];

    int tid = threadIdx.x, w = tid >> 5, lane = tid & 31;
    int g = lane >> 2, t = lane & 3;
    int wr = w % WR, wc = w / WR;
    int nb = blockIdx.x % NBL, sp = blockIdx.x / NBL;
    int z = blockIdx.z, zb = z >> 2, zh = z & 3;
    long kb0 = (long)sp * KSPL;

    const float* Ab = A + (long)zb * sAb + (long)zh * sAh + (long)(blockIdx.y * BM) * lda + kb0;
    const float* A2b = A2 ? (A2 + (long)(blockIdx.y * BM) * lda + kb0) : A;
    const float* Bb;
    if (TRB) Bb = B + (long)zb * sBb + (long)zh * sBh + (long)(nb * BN) * ldb + kb0;
    else     Bb = B + (long)zb * sBb + (long)zh * sBh + kb0 * ldb + nb * BN;

    int aR[APT], aC[APT], bR[BPT], bC[BPT];
    #pragma unroll
    for (int i = 0; i < APT; i++) {
        int s = tid + i * NTHR;
        aR[i] = s / (BK / 4); aC[i] = (s % (BK / 4)) * 4;
    }
    #pragma unroll
    for (int i = 0; i < BPT; i++) {
        int s = tid + i * NTHR;
        if (TRB) { bR[i] = s / (BK / 4); bC[i] = (s % (BK / 4)) * 4; }
        else     { bR[i] = s / (BN / 4); bC[i] = (s % (BN / 4)) * 4; }
    }
    float4 rA[APT], rB[BPT];

    auto ldg = [&](int kt) {
        int kb = kt * BK;
        #pragma unroll
        for (int i = 0; i < APT; i++) {
            float4 v = *(const float4*)(Ab + (long)aR[i] * lda + kb + aC[i]);
            if (ASUM) {
                float4 v2 = *(const float4*)(A2b + (long)aR[i] * lda + kb + aC[i]);
                v.x += v2.x; v.y += v2.y; v.z += v2.z; v.w += v2.w;
            }
            rA[i] = v;
        }
        #pragma unroll
        for (int i = 0; i < BPT; i++) {
            if (TRB) rB[i] = *(const float4*)(Bb + (long)bR[i] * ldb + kb + bC[i]);
            else     rB[i] = *(const float4*)(Bb + (long)(kb + bR[i]) * ldb + bC[i]);
        }
    };
    auto sts = [&](int bf) {
        #pragma unroll
        for (int i = 0; i < APT; i++) {
            float4 v = rA[i];
            As[bf][aC[i] + 0][aR[i]] = f2t(v.x);
            As[bf][aC[i] + 1][aR[i]] = f2t(v.y);
            As[bf][aC[i] + 2][aR[i]] = f2t(v.z);
            As[bf][aC[i] + 3][aR[i]] = f2t(v.w);
        }
        #pragma unroll
        for (int i = 0; i < BPT; i++) {
            float4 v = rB[i];
            if (TRB) {
                Bs[bf][bC[i] + 0][bR[i]] = f2t(v.x);
                Bs[bf][bC[i] + 1][bR[i]] = f2t(v.y);
                Bs[bf][bC[i] + 2][bR[i]] = f2t(v.z);
                Bs[bf][bC[i] + 3][bR[i]] = f2t(v.w);
            } else {
                *(uint4*)&Bs[bf][bR[i]][bC[i]] =
                    make_uint4(f2t(v.x), f2t(v.y), f2t(v.z), f2t(v.w));
            }
        }
    };

    float acc[2][4][4] = {};
    int wm = wr * 32, wn = wc * 32;
    int KT = KSPL / BK, buf = 0;

    ldg(0); sts(0); __syncthreads();
    for (int kt = 0; kt < KT; kt++) {
        if (kt + 1 < KT) ldg(kt + 1);
        #pragma unroll
        for (int ks = 0; ks < BK / 8; ks++) {
            unsigned af[2][4], bf_[4][2];
            #pragma unroll
            for (int mi = 0; mi < 2; mi++) {
                int m0 = wm + mi * 16 + g;
                af[mi][0] = As[buf][ks * 8 + t][m0];
                af[mi][1] = As[buf][ks * 8 + t][m0 + 8];
                af[mi][2] = As[buf][ks * 8 + t + 4][m0];
                af[mi][3] = As[buf][ks * 8 + t + 4][m0 + 8];
            }
            #pragma unroll
            for (int ni = 0; ni < 4; ni++) {
                int n0 = wn + ni * 8 + g;
                bf_[ni][0] = Bs[buf][ks * 8 + t][n0];
                bf_[ni][1] = Bs[buf][ks * 8 + t + 4][n0];
            }
            #pragma unroll
            for (int mi = 0; mi < 2; mi++)
                #pragma unroll
                for (int ni = 0; ni < 4; ni++)
                    mma8(acc[mi][ni][0], acc[mi][ni][1], acc[mi][ni][2], acc[mi][ni][3],
                         af[mi][0], af[mi][1], af[mi][2], af[mi][3],
                         bf_[ni][0], bf_[ni][1]);
        }
        if (kt + 1 < KT) { sts(buf ^ 1); __syncthreads(); buf ^= 1; }
    }

    long Cb = (long)zb * sCb + (long)zh * sCh + (long)sp * spC;
    int row0 = blockIdx.y * BM + wm;
    int col0 = nb * BN + wn;
    #pragma unroll
    for (int mi = 0; mi < 2; mi++) {
        #pragma unroll
        for (int ni = 0; ni < 4; ni++) {
            int c = col0 + ni * 8 + 2 * t;
            #pragma unroll
            for (int half = 0; half < 2; half++) {
                int r = row0 + mi * 16 + g + half * 8;
                float x = acc[mi][ni][half * 2], y = acc[mi][ni][half * 2 + 1];
                long idx = Cb + (long)r * ldc + c;
                if (EPI == EPI_BIAS)  { float2 bv = *(const float2*)(bias + c); x += bv.x; y += bv.y; }
                if (EPI == EPI_BRELU) { float2 bv = *(const float2*)(bias + c);
                                        x = fmaxf(x + bv.x, 0.f); y = fmaxf(y + bv.y, 0.f); }
                if (EPI == EPI_SC)    { float2 pv = *(const float2*)(psum + idx);
                                        x = (x + pv.x) * 0.125f; y = (y + pv.y) * 0.125f; }
                *(float2*)(C + idx) = make_float2(x, y);
            }
        }
    }
}

// ---------------- softmax over last dim (256), one warp per row --------------
__global__ void softmax_k(float* __restrict__ S) {
    int t = threadIdx.x, warp = t >> 5, lane = t & 31;
    long row = (long)blockIdx.x * 8 + warp;
    float4* rp = (float4*)(S + row * NSEQ);
    float4 a = rp[lane];
    float4 b = rp[lane + 32];
    float mx = fmaxf(fmaxf(fmaxf(a.x, a.y), fmaxf(a.z, a.w)),
                     fmaxf(fmaxf(b.x, b.y), fmaxf(b.z, b.w)));
    #pragma unroll
    for (int o = 16; o > 0; o >>= 1) mx = fmaxf(mx, __shfl_xor_sync(0xffffffffu, mx, o));
    a.x = __expf(a.x - mx); a.y = __expf(a.y - mx); a.z = __expf(a.z - mx); a.w = __expf(a.w - mx);
    b.x = __expf(b.x - mx); b.y = __expf(b.y - mx); b.z = __expf(b.z - mx); b.w = __expf(b.w - mx);
    float sm = a.x + a.y + a.z + a.w + b.x + b.y + b.z + b.w;
    #pragma unroll
    for (int o = 16; o > 0; o >>= 1) sm += __shfl_xor_sync(0xffffffffu, sm, o);
    float inv = 1.f / sm;
    a.x *= inv; a.y *= inv; a.z *= inv; a.w *= inv;
    b.x *= inv; b.y *= inv; b.z *= inv; b.w *= inv;
    rp[lane] = a; rp[lane + 32] = b;
}

// ---------------- reduce split-K partials + bias + residual + LN stats -------
template<int P>
__global__ void redres_k(const float* __restrict__ parts, const float* __restrict__ bias,
                         const float* __restrict__ R, float* __restrict__ X,
                         float* __restrict__ red) {
    __shared__ float shr[2][8];
    int gid = blockIdx.x * 256 + threadIdx.x;       // float4 index < 65536
    const float4* pp = (const float4*)parts;
    float4 a = pp[gid];
    #pragma unroll
    for (int p = 1; p < P; p++) {
        float4 v = pp[gid + p * (TOT / 4)];
        a.x += v.x; a.y += v.y; a.z += v.z; a.w += v.w;
    }
    float4 bv = ((const float4*)bias)[gid & 63];
    float4 rv = ((const float4*)R)[gid];
    a.x += bv.x + rv.x; a.y += bv.y + rv.y; a.z += bv.z + rv.z; a.w += bv.w + rv.w;
    ((float4*)X)[gid] = a;
    float s = a.x + a.y + a.z + a.w;
    float q = a.x * a.x + a.y * a.y + a.z * a.z + a.w * a.w;
    #pragma unroll
    for (int o = 16; o > 0; o >>= 1) {
        s += __shfl_xor_sync(0xffffffffu, s, o);
        q += __shfl_xor_sync(0xffffffffu, q, o);
    }
    int lane = threadIdx.x & 31, wp = threadIdx.x >> 5;
    if (lane == 0) { shr[0][wp] = s; shr[1][wp] = q; }
    __syncthreads();
    if (threadIdx.x == 0) {
        float ts = 0.f, tq = 0.f;
        #pragma unroll
        for (int i = 0; i < 8; i++) { ts += shr[0][i]; tq += shr[1][i]; }
        int bat = blockIdx.x >> 6;
        atomicAdd(&red[bat * 2], ts);
        atomicAdd(&red[bat * 2 + 1], tq);
    }
}

// ---------------- LayerNorm apply --------------------------------------------
__global__ void ln_k(const float* __restrict__ X, const float* __restrict__ w,
                     const float* __restrict__ b, const float* __restrict__ red,
                     float* __restrict__ out) {
    int gid = blockIdx.x * blockDim.x + threadIdx.x;   // < 65536 float4s
    int bt = gid >> 14;
    float m   = red[bt * 2] * (1.f / 65536.f);
    float var = red[bt * 2 + 1] * (1.f / 65536.f) - m * m;
    float ri  = rsqrtf(var + 1e-5f);
    int p = gid & 16383;
    float4 x  = ((const float4*)X)[gid];
    float4 wv = ((const float4*)w)[p];
    float4 bv = ((const float4*)b)[p];
    float4 o;
    o.x = (x.x - m) * ri * wv.x + bv.x;
    o.y = (x.y - m) * ri * wv.y + bv.y;
    o.z = (x.z - m) * ri * wv.z + bv.z;
    o.w = (x.w - m) * ri * wv.w + bv.w;
    ((float4*)out)[gid] = o;
}

// ---------------- launch ------------------------------------------------------
extern "C" void kernel_launch(void* const* d_in, const int* in_sizes, int n_in,
                              void* d_out, int out_size) {
    const float* feat = (const float*)d_in[0];
    const float* loc  = (const float*)d_in[1];
    const float* Kw   = (const float*)d_in[2];
    const float* Kb   = (const float*)d_in[3];
    const float* Qw   = (const float*)d_in[4];
    const float* Qb   = (const float*)d_in[5];
    const float* Vw   = (const float*)d_in[6];
    const float* Vb   = (const float*)d_in[7];
    const float* Fw   = (const float*)d_in[8];
    const float* Fb   = (const float*)d_in[9];
    const float* pe1w = (const float*)d_in[10];
    const float* pe1b = (const float*)d_in[11];
    const float* pe2w = (const float*)d_in[12];
    const float* pe2b = (const float*)d_in[13];
    const float* f1w  = (const float*)d_in[14];
    const float* f1b  = (const float*)d_in[15];
    const float* f2w  = (const float*)d_in[16];
    const float* f2b  = (const float*)d_in[17];
    const float* ln1w = (const float*)d_in[18];
    const float* ln1b = (const float*)d_in[19];
    const float* ln2w = (const float*)d_in[20];
    const float* ln2b = (const float*)d_in[21];
    float* out = (float*)d_out;

    float *pQKV, *pW, *pBq, *pPsum, *pS, *pAvp, *pPart, *pRes1, *pOut1, *pRes2, *pFfnh, *pRed;
    cudaGetSymbolAddress((void**)&pQKV, g_QKV);
    cudaGetSymbolAddress((void**)&pW, g_Wqkv);
    cudaGetSymbolAddress((void**)&pBq, g_Bqkv);
    cudaGetSymbolAddress((void**)&pPsum, g_psum);
    cudaGetSymbolAddress((void**)&pS, g_S);
    cudaGetSymbolAddress((void**)&pAvp, g_avp);
    cudaGetSymbolAddress((void**)&pPart, g_part);
    cudaGetSymbolAddress((void**)&pRes1, g_res1);
    cudaGetSymbolAddress((void**)&pOut1, g_out1);
    cudaGetSymbolAddress((void**)&pRes2, g_res2);
    cudaGetSymbolAddress((void**)&pFfnh, g_ffnh);
    cudaGetSymbolAddress((void**)&pRed, g_red);

    prep_k<<<193, 256>>>(Qw, Kw, Vw, Qb, Kb, Vb, pe2w, pe2b);
    pe_k<<<512, 256>>>(loc, pe1w, pe1b);

    // fused QKV projection: [1024,256] @ [256,768]
    gtc<2, 2, 32, 0, EPI_BIAS, 0, 12><<<dim3(12, 16, 1), 128>>>(
        feat, nullptr, pW, pBq, pQKV, nullptr,
        256, 256, 768, 768, 0, 0, 0, 0, 0, 0, 0);

    // scores: per (b,h), K-rows · Q-rows^T + psum, scaled
    gtc<2, 2, 32, 1, EPI_SC, 0, 4><<<dim3(4, 4, 16), 128>>>(
        pQKV + 256, nullptr, pQKV, nullptr, pS, pPsum,
        64, 768, 768, 256, 196608, 64, 196608, 64, 262144, 65536, 0);

    softmax_k<<<512, 256>>>(pS);

    // merged = attn @ V (split-K 2 -> partials, summed in Fproj A-load)
    gtc<2, 2, 32, 0, EPI_NONE, 0, 1><<<dim3(2, 4, 16), 128>>>(
        pS, nullptr, pQKV + 512, nullptr, pAvp, nullptr,
        128, 256, 768, 256, 262144, 65536, 196608, 64, 65536, 64, TOT);

    // output projection (split-K 2 over K=256, A = avp0+avp1)
    gtc<2, 2, 32, 0, EPI_NONE, 1, 4><<<dim3(8, 16, 1), 128>>>(
        pAvp, pAvp + TOT, Fw, nullptr, pPart, nullptr,
        128, 256, 256, 256, 0, 0, 0, 0, 0, 0, TOT);

    redres_k<2><<<256, 256>>>(pPart, Fb, feat, pRes1, pRed);
    ln_k<<<256, 256>>>(pRes1, ln1w, ln1b, pRed, pOut1);

    // FFN1: [1024,256] @ [256,1024], bias+relu
    gtc<2, 2, 32, 0, EPI_BRELU, 0, 16><<<dim3(16, 16, 1), 128>>>(
        pOut1, nullptr, f1w, f1b, pFfnh, nullptr,
        256, 256, 1024, 1024, 0, 0, 0, 0, 0, 0, 0);

    // FFN2: [1024,1024] @ [1024,256], split-K 4
    gtc<2, 2, 32, 0, EPI_NONE, 0, 4><<<dim3(16, 16, 1), 128>>>(
        pFfnh, nullptr, f2w, nullptr, pPart, nullptr,
        256, 1024, 256, 256, 0, 0, 0, 0, 0, 0, TOT);

    redres_k<4><<<256, 256>>>(pPart, f2b, pOut1, pRes2, pRed + 8);
    ln_k<<<256, 256>>>(pRes2, ln2w, ln2b, pRed + 8, out);
}